// round 5
// baseline (speedup 1.0000x reference)
#include <cuda_runtime.h>
#include <cstdint>

#define NGROUP 80
#define BEX 8
#define NPG 1024
#define MCENT 512
#define NTHR 512
#define MAXIT 300
#define TOLF 1e-3f

typedef unsigned long long u64;

// ---------------- device globals (no allocation allowed) ----------------
__device__ int g_starts[NGROUP];
__device__ int g_flags[MAXIT + 1];
__device__ unsigned int g_bar_count;   // returns to 0 after each barrier
__device__ unsigned int g_bar_gen;     // monotonically increasing across replays (safe)

// ---------------- threefry2x32 (exact JAX PRNG, partitionable scheme) ----------------
__device__ __forceinline__ uint32_t rotl32(uint32_t x, int d) { return (x << d) | (x >> (32 - d)); }

__device__ void tf2x32(uint32_t k0, uint32_t k1, uint32_t x0, uint32_t x1,
                       uint32_t& o0, uint32_t& o1) {
    uint32_t ks0 = k0, ks1 = k1, ks2 = k0 ^ k1 ^ 0x1BD11BDAu;
#define RND(r) { x0 += x1; x1 = rotl32(x1, r); x1 ^= x0; }
    x0 += ks0; x1 += ks1;
    RND(13) RND(15) RND(26) RND(6)   x0 += ks1; x1 += ks2 + 1u;
    RND(17) RND(29) RND(16) RND(24)  x0 += ks2; x1 += ks0 + 2u;
    RND(13) RND(15) RND(26) RND(6)   x0 += ks0; x1 += ks1 + 3u;
    RND(17) RND(29) RND(16) RND(24)  x0 += ks1; x1 += ks2 + 4u;
    RND(13) RND(15) RND(26) RND(6)   x0 += ks2; x1 += ks0 + 5u;
#undef RND
    o0 = x0; o1 = x1;
}

__global__ void starts_kernel() {
    int i = threadIdx.x;
    if (i >= NGROUP) return;
    uint32_t c0, c1;
    tf2x32(0u, 1u, 0u, 1u, c0, c1);          // k2 = split(key(1))[1] (partitionable)
    uint32_t o0, o1;
    tf2x32(c0, c1, 0u, (uint32_t)i, o0, o1); // 64-bit counter (0, i)
    g_starts[i] = (int)((o0 ^ o1) & 1023u);
}

// ---------------- grid barrier (80 blocks, all co-resident) ----------------
__device__ void grid_barrier() {
    __syncthreads();
    if (threadIdx.x == 0) {
        volatile unsigned int* vgen = &g_bar_gen;
        unsigned int gen = *vgen;
        __threadfence();
        unsigned int ticket = atomicAdd(&g_bar_count, 1u);
        if (ticket == NGROUP - 1) {
            g_bar_count = 0u;
            __threadfence();
            atomicAdd(&g_bar_gen, 1u);
        } else {
            while (*vgen == gen) { __nanosleep(32); }
        }
        __threadfence();
    }
    __syncthreads();
}

__device__ __forceinline__ float sq3(float a, float b, float c) {
    // ((a*a + b*b) + c*c), non-fused (reference-critical math)
    return __fadd_rn(__fadd_rn(__fmul_rn(a, a), __fmul_rn(b, b)), __fmul_rn(c, c));
}

// ---------------- packed f32x2 helpers ----------------
__device__ __forceinline__ void pack2(float a, float b, u64& r) {
    asm("mov.b64 %0, {%1,%2};" : "=l"(r) : "f"(a), "f"(b));
}
__device__ __forceinline__ void unpack2(u64 v, float& lo, float& hi) {
    asm("mov.b64 {%0,%1}, %2;" : "=f"(lo), "=f"(hi) : "l"(v));
}
__device__ __forceinline__ u64 fma2(u64 a, u64 b, u64 c) {
    u64 d; asm("fma.rn.f32x2 %0, %1, %2, %3;" : "=l"(d) : "l"(a), "l"(b), "l"(c)); return d;
}
__device__ __forceinline__ u64 add2(u64 a, u64 b) {
    u64 d; asm("add.rn.f32x2 %0, %1, %2;" : "=l"(d) : "l"(a), "l"(b)); return d;
}
__device__ __forceinline__ u64 mul2(u64 a, u64 b) {
    u64 d; asm("mul.rn.f32x2 %0, %1, %2;" : "=l"(d) : "l"(a), "l"(b)); return d;
}

// ---------------- main persistent kernel: FPS + k-means + score ----------------
__global__ void __launch_bounds__(NTHR, 1)
kmeans_kernel(const float* __restrict__ pos, float* __restrict__ out, int out_size) {
    __shared__ float4   sP[NPG];          // points                             16384 B
    // centroid pairs, SoA: [p*4+0]=(-2cx)2  [p*4+1]=(-2cy)2  [p*4+2]=(-2cz)2  [p*4+3]=(c2)2
    __shared__ u64      sC2[MCENT * 2];   //                                     8192 B
    __shared__ uint8_t  whist[32][MCENT]; // rows 0-15: A-points, 16-31: B      16384 B
    __shared__ uint16_t sortIdx[NPG];     // cluster-sorted point indices        2048 B
    __shared__ uint16_t sCnt[MCENT];
    __shared__ uint16_t sOff[MCENT];
    __shared__ uint32_t sWsum[16];
    __shared__ uint32_t redVI[2][8];      // FPS: {v0..v3, i0..i3} per parity
    __shared__ float    redF[16];
    __shared__ float    sScore;

    const int g = blockIdx.x;
    const int t = threadIdx.x;
    const int b = g & (BEX - 1);           // group g = r*B + b  ->  example b
    const float* pb = pos + (size_t)b * NPG * 3;

    // two points per thread: A = t, B = t + 512
    const float pxA = pb[t * 3 + 0], pyA = pb[t * 3 + 1], pzA = pb[t * 3 + 2];
    const float pxB = pb[(t + NTHR) * 3 + 0], pyB = pb[(t + NTHR) * 3 + 1], pzB = pb[(t + NTHR) * 3 + 2];
    sP[t]        = make_float4(pxA, pyA, pzA, 0.f);
    sP[t + NTHR] = make_float4(pxB, pyB, pzB, 0.f);
    __syncthreads();

    const int wid = t >> 5, lane = t & 31;
    float* sCf = (float*)sC2;             // float view: [p*8 + field*2 + half]

    // ================= FPS init: warps 0-3 only, 8 points/thread =================
    if (t < 128) {
        u64 px2[4], py2[4], pz2[4];
        float mindv[8];
        #pragma unroll
        for (int i = 0; i < 4; ++i) {
            float4 a = sP[t + 256 * i];         // global idx t + 128*(2i)
            float4 c = sP[t + 256 * i + 128];   // global idx t + 128*(2i+1)
            pack2(a.x, c.x, px2[i]);
            pack2(a.y, c.y, py2[i]);
            pack2(a.z, c.z, pz2[i]);
            mindv[2 * i]     = __int_as_float(0x7f800000);
            mindv[2 * i + 1] = __int_as_float(0x7f800000);
        }
        int last = g_starts[g];
        for (int k = 0; k < MCENT; ++k) {
            float4 q = sP[last];               // uniform broadcast
            if (t == 0) {                      // write packed centroid for assign
                int p = k >> 1, h = k & 1;
                sCf[p * 8 + 0 + h] = __fmul_rn(-2.0f, q.x);
                sCf[p * 8 + 2 + h] = __fmul_rn(-2.0f, q.y);
                sCf[p * 8 + 4 + h] = __fmul_rn(-2.0f, q.z);
                sCf[p * 8 + 6 + h] = sq3(q.x, q.y, q.z);
            }
            u64 nqx, nqy, nqz;
            pack2(-q.x, -q.x, nqx); pack2(-q.y, -q.y, nqy); pack2(-q.z, -q.z, nqz);
            #pragma unroll
            for (int i = 0; i < 4; ++i) {
                // exact reference math per half: dx=px+(-qx); (dx*dx+dy*dy)+dz*dz
                u64 dx = add2(px2[i], nqx);
                u64 dy = add2(py2[i], nqy);
                u64 dz = add2(pz2[i], nqz);
                u64 s1 = add2(mul2(dx, dx), mul2(dy, dy));
                u64 d2 = add2(s1, mul2(dz, dz));
                float lo, hi; unpack2(d2, lo, hi);
                mindv[2 * i]     = fminf(mindv[2 * i], lo);
                mindv[2 * i + 1] = fminf(mindv[2 * i + 1], hi);
            }
            // thread-local argmax, first (smallest global) index on ties
            uint32_t curv = __float_as_uint(mindv[0]);   // mind >= 0: bits monotonic
            uint32_t curi = (uint32_t)t;
            #pragma unroll
            for (int s = 1; s < 8; ++s) {
                uint32_t v = __float_as_uint(mindv[s]);
                if (v > curv) { curv = v; curi = (uint32_t)(t + (s << 7)); }
            }
            uint32_t wm  = __reduce_max_sync(0xffffffffu, curv);
            uint32_t cnd = (curv == wm) ? curi : 0xFFFFu;
            uint32_t wix = __reduce_min_sync(0xffffffffu, cnd);
            int par = k & 1;
            if (lane == 0) { redVI[par][wid] = wm; redVI[par][4 + wid] = wix; }
            asm volatile("bar.sync 1, 128;" ::: "memory");
            uint4 vv = *(const uint4*)&redVI[par][0];
            uint4 ii = *(const uint4*)&redVI[par][4];
            uint32_t cv = vv.x, ci = ii.x;
            if (vv.y > cv || (vv.y == cv && ii.y < ci)) { cv = vv.y; ci = ii.y; }
            if (vv.z > cv || (vv.z == cv && ii.z < ci)) { cv = vv.z; ci = ii.z; }
            if (vv.w > cv || (vv.w == cv && ii.w < ci)) { cv = vv.w; ci = ii.w; }
            last = (int)ci;
        }
    }
    __syncthreads();   // centroids visible to all; warps 4-15 waited here

    // point coords packed once for the assign loop
    u64 px2A, py2A, pz2A, px2B, py2B, pz2B;
    pack2(pxA, pxA, px2A); pack2(pyA, pyA, py2A); pack2(pzA, pzA, pz2A);
    pack2(pxB, pxB, px2B); pack2(pyB, pyB, py2B); pack2(pzB, pzB, pz2B);
    const ulonglong2* sC2v = (const ulonglong2*)sC2;

    // ================= k-means loop (global lockstep) =================
    int bjA = 0, bjB = 0;
    for (int iter = 0; iter < MAXIT; ++iter) {
        // ---- assign: argmin_j (c2 + px*(-2cx) + py*(-2cy) + pz*(-2cz)), packed 2j/step ----
        float bestA = __int_as_float(0x7f800000);
        float bestB = __int_as_float(0x7f800000);
        bjA = 0; bjB = 0;
        #pragma unroll 4
        for (int p = 0; p < MCENT / 2; ++p) {
            ulonglong2 m0 = sC2v[2 * p];       // (-2cx)2, (-2cy)2
            ulonglong2 m1 = sC2v[2 * p + 1];   // (-2cz)2, (c2)2
            u64 accA = fma2(pz2A, m1.x, fma2(py2A, m0.y, fma2(px2A, m0.x, m1.y)));
            float alo, ahi; unpack2(accA, alo, ahi);
            if (alo < bestA) { bestA = alo; bjA = 2 * p; }       // strict '<': first index
            if (ahi < bestA) { bestA = ahi; bjA = 2 * p + 1; }
            u64 accB = fma2(pz2B, m1.x, fma2(py2B, m0.y, fma2(px2B, m0.x, m1.y)));
            float blo, bhi; unpack2(accB, blo, bhi);
            if (blo < bestB) { bestB = blo; bjB = 2 * p; }
            if (bhi < bestB) { bestB = bhi; bjB = 2 * p + 1; }
        }

        // ---- deterministic stable counting sort of points by cluster ----
        ((uint4*)whist)[t * 2]     = make_uint4(0u, 0u, 0u, 0u);   // zero 16KB
        ((uint4*)whist)[t * 2 + 1] = make_uint4(0u, 0u, 0u, 0u);
        __syncthreads();

        uint32_t below = (1u << lane) - 1u;
        uint32_t mmA = __match_any_sync(0xffffffffu, (uint32_t)bjA);
        int riwA = __popc(mmA & below);
        if (riwA == 0) whist[wid][bjA] = (uint8_t)__popc(mmA);
        uint32_t mmB = __match_any_sync(0xffffffffu, (uint32_t)bjB);
        int riwB = __popc(mmB & below);
        if (riwB == 0) whist[16 + wid][bjB] = (uint8_t)__popc(mmB);
        __syncthreads();

        // per-cluster exclusive prefix over the 32 rows (in place) + counts
        uint32_t run = 0;
        #pragma unroll
        for (int w = 0; w < 32; ++w) {
            uint32_t v = whist[w][t];
            whist[w][t] = (uint8_t)run;
            run += v;
        }
        sCnt[t] = (uint16_t)run;

        // block-wide exclusive prefix sum over the 512 counts (16 warps)
        uint32_t x = run;
        #pragma unroll
        for (int o = 1; o < 32; o <<= 1) {
            uint32_t y = __shfl_up_sync(0xffffffffu, x, o);
            if (lane >= o) x += y;
        }
        uint32_t exclInWarp = x - run;
        if (lane == 31) sWsum[wid] = x;
        __syncthreads();
        if (wid == 0) {
            uint32_t wv = (lane < 16) ? sWsum[lane] : 0u;
            uint32_t xx = wv;
            #pragma unroll
            for (int o = 1; o < 16; o <<= 1) {
                uint32_t y = __shfl_up_sync(0xffffffffu, xx, o);
                if (lane >= o) xx += y;
            }
            if (lane < 16) sWsum[lane] = xx - wv;
        }
        __syncthreads();
        sOff[t] = (uint16_t)(sWsum[wid] + exclInWarp);
        __syncthreads();

        // scatter point indices; ascending-index order preserved per cluster
        {
            uint32_t rkA = (uint32_t)sOff[bjA] + whist[wid][bjA] + (uint32_t)riwA;
            sortIdx[rkA] = (uint16_t)t;
            uint32_t rkB = (uint32_t)sOff[bjB] + whist[16 + wid][bjB] + (uint32_t)riwB;
            sortIdx[rkB] = (uint16_t)(t + NTHR);
        }
        __syncthreads();

        // per-cluster ordered fold + centroid update + convergence
        int moved = 0;
        {
            uint32_t n = sCnt[t], base = sOff[t];
            float sx = 0.f, sy = 0.f, sz = 0.f;
            for (uint32_t k2 = 0; k2 < n; ++k2) {
                float4 p = sP[sortIdx[base + k2]];
                sx = __fadd_rn(sx, p.x);
                sy = __fadd_rn(sy, p.y);
                sz = __fadd_rn(sz, p.z);
            }
            int pp = t >> 1, h = t & 1;
            float ocx = __fmul_rn(-0.5f, sCf[pp * 8 + 0 + h]);   // exact recovery
            float ocy = __fmul_rn(-0.5f, sCf[pp * 8 + 2 + h]);
            float ocz = __fmul_rn(-0.5f, sCf[pp * 8 + 4 + h]);
            float cntf = (float)n;
            float nx, ny, nz;
            if (n > 0) {
                nx = __fdiv_rn(sx, cntf); ny = __fdiv_rn(sy, cntf); nz = __fdiv_rn(sz, cntf);
            } else {
                nx = ocx; ny = ocy; nz = ocz;
            }
            float dx = __fsub_rn(ocx, nx), dy = __fsub_rn(ocy, ny), dz = __fsub_rn(ocz, nz);
            moved = !(sqrtf(sq3(dx, dy, dz)) < TOLF);
            sCf[pp * 8 + 0 + h] = __fmul_rn(-2.0f, nx);
            sCf[pp * 8 + 2 + h] = __fmul_rn(-2.0f, ny);
            sCf[pp * 8 + 4 + h] = __fmul_rn(-2.0f, nz);
            sCf[pp * 8 + 6 + h] = sq3(nx, ny, nz);
        }
        int any = __syncthreads_or(moved);
        if (t == 0 && any) atomicOr(&g_flags[iter], 1);
        grid_barrier();
        int notdone = *((volatile int*)&g_flags[iter]);
        if (!notdone) break;   // all blocks agree -> same iteration count everywhere
    }

    // ================= score: L1 to assigned (final) centroids =================
    {
        int pA = bjA >> 1, hA = bjA & 1;
        float cax = __fmul_rn(-0.5f, sCf[pA * 8 + 0 + hA]);
        float cay = __fmul_rn(-0.5f, sCf[pA * 8 + 2 + hA]);
        float caz = __fmul_rn(-0.5f, sCf[pA * 8 + 4 + hA]);
        int pB = bjB >> 1, hB = bjB & 1;
        float cbx = __fmul_rn(-0.5f, sCf[pB * 8 + 0 + hB]);
        float cby = __fmul_rn(-0.5f, sCf[pB * 8 + 2 + hB]);
        float cbz = __fmul_rn(-0.5f, sCf[pB * 8 + 4 + hB]);
        float s = fabsf(pxA - cax) + fabsf(pyA - cay) + fabsf(pzA - caz)
                + fabsf(pxB - cbx) + fabsf(pyB - cby) + fabsf(pzB - cbz);
        #pragma unroll
        for (int off = 16; off > 0; off >>= 1)
            s += __shfl_down_sync(0xffffffffu, s, off);
        if (lane == 0) redF[wid] = s;
        __syncthreads();
        if (wid == 0) {
            float v = (lane < 16) ? redF[lane] : 0.f;
            #pragma unroll
            for (int off = 8; off > 0; off >>= 1)
                v += __shfl_down_sync(0xffffffffu, v, off);
            if (lane == 0) sScore = v;
        }
        __syncthreads();
    }

    // ================= outputs: [classification | centroids | scores] =================
    int ci = g * NPG + t;
    if (ci < out_size) out[ci] = (float)bjA;
    int ci2 = g * NPG + NTHR + t;
    if (ci2 < out_size) out[ci2] = (float)bjB;
    {
        int base = NGROUP * NPG + g * (MCENT * 3) + t * 3;
        if (base + 2 < out_size) {
            int pp = t >> 1, h = t & 1;
            out[base + 0] = __fmul_rn(-0.5f, sCf[pp * 8 + 0 + h]);
            out[base + 1] = __fmul_rn(-0.5f, sCf[pp * 8 + 2 + h]);
            out[base + 2] = __fmul_rn(-0.5f, sCf[pp * 8 + 4 + h]);
        }
    }
    if (t == 0) {
        int si = NGROUP * NPG + NGROUP * MCENT * 3 + g;
        if (si < out_size) out[si] = sScore;
    }
}

extern "C" void kernel_launch(void* const* d_in, const int* in_sizes, int n_in,
                              void* d_out, int out_size) {
    const float* pos = (const float*)d_in[0];
    void* flagsAddr = nullptr;
    cudaGetSymbolAddress(&flagsAddr, g_flags);
    cudaMemsetAsync(flagsAddr, 0, sizeof(int) * (MAXIT + 1), 0);
    starts_kernel<<<1, 128>>>();
    kmeans_kernel<<<NGROUP, NTHR>>>(pos, (float*)d_out, out_size);
}